// round 11
// baseline (speedup 1.0000x reference)
#include <cuda_runtime.h>
#include <cstdint>
#include <cstddef>

// Problem constants
#define PB   8
#define PS   1024
#define PHQ  32
#define PHKV 8
#define PD   128
#define BM   64
#define BN   64
#define NTHREADS 256

// smem strides (floats) — all mma fragment accesses conflict-free:
//  Qs/Ks stride 132: bank(4*lr+lc) distinct over warp
//  Vs stride 136:    bank(8*lc+lr) distinct
//  Ps stride 68:     bank(4*lr+lc) distinct
#define QS_STRIDE 132
#define KS_STRIDE 132
#define VS_STRIDE 136
#define PST       68

#define QS_OFF  0
#define KS_OFF  (BM * QS_STRIDE)                  // 8448 floats
#define VS_OFF  (KS_OFF + BN * KS_STRIDE)         // 16896
#define SUM_OFF (VS_OFF + BN * VS_STRIDE)         // 25600
#define SMEM_FLOATS (SUM_OFF + 2 * BM)            // 25728
#define SMEM_BYTES  (SMEM_FLOATS * 4)             // 102912 B -> 2 CTAs/SM

static __device__ __forceinline__ float ex2f(float x) {
    float y; asm("ex2.approx.f32 %0, %1;" : "=f"(y) : "f"(x)); return y;
}
static __device__ __forceinline__ uint32_t tf32r(float x) {
    uint32_t u; asm("cvt.rna.tf32.f32 %0, %1;" : "=r"(u) : "f"(x)); return u;
}
static __device__ __forceinline__ uint32_t smem_u32(const void* p) {
    uint32_t a;
    asm("{ .reg .u64 t; cvta.to.shared.u64 t, %1; cvt.u32.u64 %0, t; }" : "=r"(a) : "l"(p));
    return a;
}
static __device__ __forceinline__ void cp16(uint32_t dst, const void* src) {
    asm volatile("cp.async.cg.shared.global [%0], [%1], 16;" :: "r"(dst), "l"(src));
}
static __device__ __forceinline__ void cp_commit() {
    asm volatile("cp.async.commit_group;" ::: "memory");
}
template <int N> static __device__ __forceinline__ void cp_wait() {
    asm volatile("cp.async.wait_group %0;" :: "n"(N) : "memory");
}
static __device__ __forceinline__ void mma_tf32(float c[4], const uint32_t a[4],
                                                uint32_t b0, uint32_t b1) {
    asm volatile("mma.sync.aligned.m16n8k8.row.col.f32.tf32.tf32.f32 "
                 "{%0,%1,%2,%3}, {%4,%5,%6,%7}, {%8,%9}, {%0,%1,%2,%3};"
                 : "+f"(c[0]), "+f"(c[1]), "+f"(c[2]), "+f"(c[3])
                 : "r"(a[0]), "r"(a[1]), "r"(a[2]), "r"(a[3]), "r"(b0), "r"(b1));
}

__global__ __launch_bounds__(NTHREADS, 2)
void fa_mma4_kernel(const float* __restrict__ q,
                    const float* __restrict__ k,
                    const float* __restrict__ v,
                    float* __restrict__ out)
{
    extern __shared__ float smf[];
    uint32_t* QsU = reinterpret_cast<uint32_t*>(smf + QS_OFF);
    const uint32_t* KsU = reinterpret_cast<const uint32_t*>(smf + KS_OFF);
    uint32_t* VsU = reinterpret_cast<uint32_t*>(smf + VS_OFF);
    uint32_t* PsU = reinterpret_cast<uint32_t*>(smf + KS_OFF);  // P overlays retired K
    float*    sums = smf + SUM_OFF;      // [2][64]
    const uint32_t sbase = smem_u32(smf);

    const int m_tile = (int)gridDim.x - 1 - (int)blockIdx.x;  // longest first
    const int h  = blockIdx.y;
    const int b  = blockIdx.z;
    const int hk = h >> 2;
    const int m0 = m_tile * BM;
    const int NT = m_tile + 1;

    const int tid  = threadIdx.x;
    const int wid  = tid >> 5;           // 0..7
    const int lane = tid & 31;
    const int lr   = lane >> 2;          // 0..7
    const int lc   = lane & 3;           // 0..3
    const int warp_m  = (wid >> 1) * 16; // S/O row base (0..48)
    const int warp_nS = (wid & 1) * 32;  // S col base
    const int warp_nO = (wid & 1) * 64;  // O col base

    // ---- prefetch K(0), V(0) as two cp.async groups ----
    {
        #pragma unroll
        for (int j = 0; j < 8; ++j) {
            const int i = tid + j * NTHREADS;
            const int row = i >> 5, d4 = i & 31;
            const size_t gb = ((size_t)(b * PS + row) * PHKV + hk) * PD + (d4 << 2);
            cp16(sbase + (uint32_t)(KS_OFF + row * KS_STRIDE + (d4 << 2)) * 4u, k + gb);
        }
        cp_commit();
        #pragma unroll
        for (int j = 0; j < 8; ++j) {
            const int i = tid + j * NTHREADS;
            const int row = i >> 5, d4 = i & 31;
            const size_t gb = ((size_t)(b * PS + row) * PHKV + hk) * PD + (d4 << 2);
            cp16(sbase + (uint32_t)(VS_OFF + row * VS_STRIDE + (d4 << 2)) * 4u, v + gb);
        }
        cp_commit();
    }

    // ---- stage Q (tf32 rna, pre-scaled by (1/sqrt(D))*log2(e)) ----
    const float qscale = 0.08838834764831845f * 1.4426950408889634f;
    for (int i = tid; i < BM * (PD / 4); i += NTHREADS) {
        const int row = i >> 5, d4 = i & 31;
        const float4 val = *reinterpret_cast<const float4*>(
            q + ((size_t)(b * PS + m0 + row) * PHQ + h) * PD + (d4 << 2));
        uint4 t;
        t.x = tf32r(val.x * qscale); t.y = tf32r(val.y * qscale);
        t.z = tf32r(val.z * qscale); t.w = tf32r(val.w * qscale);
        *reinterpret_cast<uint4*>(QsU + row * QS_STRIDE + (d4 << 2)) = t;
    }

    float oc[8][4];
    #pragma unroll
    for (int ni = 0; ni < 8; ++ni)
        #pragma unroll
        for (int j = 0; j < 4; ++j) oc[ni][j] = 0.0f;
    float ls[2] = {0.f, 0.f};

    for (int nt = 0; nt < NT; ++nt) {
        const int n0 = nt * BN;

        cp_wait<1>();      // K(nt) landed (V(nt) may still be in flight)
        __syncthreads();   // S2: K visible block-wide

        // ---- S = Q K^T : warp tile 16x32, m16n8k8 x (4 ni, 16 ks) ----
        float sc[4][4];
        #pragma unroll
        for (int ni = 0; ni < 4; ++ni)
            #pragma unroll
            for (int j = 0; j < 4; ++j) sc[ni][j] = 0.0f;

        #pragma unroll
        for (int ks = 0; ks < 16; ++ks) {
            const int k0 = ks * 8;
            uint32_t a[4];
            {
                const uint32_t* q0 = QsU + (warp_m + lr) * QS_STRIDE + k0 + lc;
                a[0] = q0[0];
                a[1] = q0[8 * QS_STRIDE];
                a[2] = q0[4];
                a[3] = q0[8 * QS_STRIDE + 4];
            }
            #pragma unroll
            for (int ni = 0; ni < 4; ++ni) {
                const uint32_t* kp = KsU + (warp_nS + ni * 8 + lr) * KS_STRIDE + k0 + lc;
                mma_tf32(sc[ni], a, kp[0], kp[4]);
            }
        }

        // ---- softmax: p = exp2(s), unnormalized; causal mask on diagonal ----
        const bool diag = (nt == m_tile);
        {
            const int r0g = m0 + warp_m + lr;
            #pragma unroll
            for (int ni = 0; ni < 4; ++ni) {
                float* c = sc[ni];
                const int cb = n0 + warp_nS + ni * 8 + 2 * lc;
                float p0, p1, p2, p3;
                if (diag) {
                    p0 = (cb     <= r0g    ) ? ex2f(c[0]) : 0.0f;
                    p1 = (cb + 1 <= r0g    ) ? ex2f(c[1]) : 0.0f;
                    p2 = (cb     <= r0g + 8) ? ex2f(c[2]) : 0.0f;
                    p3 = (cb + 1 <= r0g + 8) ? ex2f(c[3]) : 0.0f;
                } else {
                    p0 = ex2f(c[0]); p1 = ex2f(c[1]);
                    p2 = ex2f(c[2]); p3 = ex2f(c[3]);
                }
                ls[0] += p0 + p1;
                ls[1] += p2 + p3;
                c[0] = p0; c[1] = p1; c[2] = p2; c[3] = p3;
            }
        }
        __syncthreads();   // S2b: all warps done reading Ks before P overwrite

        // ---- store P (tf32 rna) into Ps (overlays Ks) ----
        {
            const int rl = warp_m + lr;
            #pragma unroll
            for (int ni = 0; ni < 4; ++ni) {
                uint32_t* pd = PsU + rl * PST + warp_nS + ni * 8 + 2 * lc;
                uint2 u01, u23;
                u01.x = tf32r(sc[ni][0]); u01.y = tf32r(sc[ni][1]);
                u23.x = tf32r(sc[ni][2]); u23.y = tf32r(sc[ni][3]);
                *reinterpret_cast<uint2*>(pd)           = u01;
                *reinterpret_cast<uint2*>(pd + 8 * PST) = u23;
            }
        }
        cp_wait<0>();      // V(nt) landed
        __syncthreads();   // S3: P + V visible

        // ---- O += P V : warp tile 16x128, m16n8k8 x (8 ni, 8 ks) ----
        #pragma unroll
        for (int ks = 0; ks < 8; ++ks) {
            const int k0 = ks * 8;
            uint32_t a[4];
            {
                const uint32_t* pp = PsU + (warp_m + lr) * PST + k0 + lc;
                a[0] = pp[0];
                a[1] = pp[8 * PST];
                a[2] = pp[4];
                a[3] = pp[8 * PST + 4];
            }
            #pragma unroll
            for (int ni = 0; ni < 8; ++ni) {
                const uint32_t* vp = VsU + (k0 + lc) * VS_STRIDE + warp_nO + ni * 8 + lr;
                mma_tf32(oc[ni], a, vp[0], vp[4 * VS_STRIDE]);
            }
        }

        // ---- issue K(nt+1), V(nt+1) after P/K and V are dead ----
        if (nt + 1 < NT) {
            const int n1 = n0 + BN;
            __syncthreads();   // S1: PV done block-wide; K/P and V buffers free
            #pragma unroll
            for (int j = 0; j < 8; ++j) {
                const int i = tid + j * NTHREADS;
                const int row = i >> 5, d4 = i & 31;
                const size_t gb = ((size_t)(b * PS + n1 + row) * PHKV + hk) * PD + (d4 << 2);
                cp16(sbase + (uint32_t)(KS_OFF + row * KS_STRIDE + (d4 << 2)) * 4u, k + gb);
            }
            cp_commit();
            #pragma unroll
            for (int j = 0; j < 8; ++j) {
                const int i = tid + j * NTHREADS;
                const int row = i >> 5, d4 = i & 31;
                const size_t gb = ((size_t)(b * PS + n1 + row) * PHKV + hk) * PD + (d4 << 2);
                cp16(sbase + (uint32_t)(VS_OFF + row * VS_STRIDE + (d4 << 2)) * 4u, v + gb);
            }
            cp_commit();
        }
    }

    // ---- epilogue: rowsum reduce (pair lanes, then warp pair), normalize, store ----
    #pragma unroll
    for (int i = 0; i < 2; ++i) {
        ls[i] += __shfl_xor_sync(0xffffffffu, ls[i], 1);
        ls[i] += __shfl_xor_sync(0xffffffffu, ls[i], 2);
    }
    __syncthreads();
    if (lc == 0) {
        #pragma unroll
        for (int half = 0; half < 2; ++half)
            sums[(wid & 1) * BM + warp_m + half * 8 + lr] = ls[half];
    }
    __syncthreads();

    #pragma unroll
    for (int half = 0; half < 2; ++half) {
        const int rl = warp_m + half * 8 + lr;
        const float inv = 1.0f / (sums[rl] + sums[BM + rl]);
        float* op = out + ((size_t)(b * PS + m0 + rl) * PHQ + h) * PD
                    + warp_nO + 2 * lc;
        #pragma unroll
        for (int ni = 0; ni < 8; ++ni) {
            float2 o;
            o.x = oc[ni][half * 2 + 0] * inv;
            o.y = oc[ni][half * 2 + 1] * inv;
            *reinterpret_cast<float2*>(op + ni * 8) = o;
        }
    }
}

extern "C" void kernel_launch(void* const* d_in, const int* in_sizes, int n_in,
                              void* d_out, int out_size) {
    // The reference's paged-cache scatter/gather is an exact identity
    // (distinct slots written then immediately gathered), so only q,k,v matter.
    const float* q = (const float*)d_in[0];
    const float* k = (const float*)d_in[1];
    const float* v = (const float*)d_in[2];
    float* out = (float*)d_out;

    cudaFuncSetAttribute(fa_mma4_kernel,
                         cudaFuncAttributeMaxDynamicSharedMemorySize, SMEM_BYTES);

    dim3 grid(PS / BM, PHQ, PB);   // (16, 32, 8) = 4096 CTAs
    fa_mma4_kernel<<<grid, NTHREADS, SMEM_BYTES>>>(q, k, v, out);
}

// round 12
// speedup vs baseline: 1.2498x; 1.2498x over previous
#include <cuda_runtime.h>
#include <cstdint>
#include <cstddef>

// Problem constants
#define PB   8
#define PS   1024
#define PHQ  32
#define PHKV 8
#define PD   128
#define BM   128
#define BN   32
#define NTHREADS 128

// smem strides (floats):
//  Qs/Ks stride 132 (≡4 mod 32): fragment LDS banks = 4*lr+lc, conflict-free
//  Vs stride 136 (≡8 mod 32):    fragment LDS banks = 8*lc+lr, conflict-free
#define QS_STRIDE 132
#define KS_STRIDE 132
#define VS_STRIDE 136

#define QS_OFF  0
#define KS_OFF  (BM * QS_STRIDE)                  // 16896 floats
#define VS_OFF  (KS_OFF + BN * KS_STRIDE)         // 21120
#define SMEM_FLOATS (VS_OFF + BN * VS_STRIDE)     // 25472
#define SMEM_BYTES  (SMEM_FLOATS * 4)             // 101888 B -> 2 CTAs/SM

static __device__ __forceinline__ float ex2f(float x) {
    float y; asm("ex2.approx.f32 %0, %1;" : "=f"(y) : "f"(x)); return y;
}
static __device__ __forceinline__ uint32_t tf32r(float x) {
    uint32_t u; asm("cvt.rna.tf32.f32 %0, %1;" : "=r"(u) : "f"(x)); return u;
}
static __device__ __forceinline__ uint32_t smem_u32(const void* p) {
    uint32_t a;
    asm("{ .reg .u64 t; cvta.to.shared.u64 t, %1; cvt.u32.u64 %0, t; }" : "=r"(a) : "l"(p));
    return a;
}
static __device__ __forceinline__ void cp16(uint32_t dst, const void* src) {
    asm volatile("cp.async.cg.shared.global [%0], [%1], 16;" :: "r"(dst), "l"(src));
}
static __device__ __forceinline__ void cp_commit() {
    asm volatile("cp.async.commit_group;" ::: "memory");
}
template <int N> static __device__ __forceinline__ void cp_wait() {
    asm volatile("cp.async.wait_group %0;" :: "n"(N) : "memory");
}
static __device__ __forceinline__ void mma_tf32(float c[4], const uint32_t a[4],
                                                uint32_t b0, uint32_t b1) {
    asm volatile("mma.sync.aligned.m16n8k8.row.col.f32.tf32.tf32.f32 "
                 "{%0,%1,%2,%3}, {%4,%5,%6,%7}, {%8,%9}, {%0,%1,%2,%3};"
                 : "+f"(c[0]), "+f"(c[1]), "+f"(c[2]), "+f"(c[3])
                 : "r"(a[0]), "r"(a[1]), "r"(a[2]), "r"(a[3]), "r"(b0), "r"(b1));
}

__global__ __launch_bounds__(NTHREADS, 2)
void fa_mma5_kernel(const float* __restrict__ q,
                    const float* __restrict__ k,
                    const float* __restrict__ v,
                    float* __restrict__ out)
{
    extern __shared__ float smf[];
    uint32_t* QsU = reinterpret_cast<uint32_t*>(smf + QS_OFF);
    const uint32_t* KsU = reinterpret_cast<const uint32_t*>(smf + KS_OFF);
    const uint32_t* VsU = reinterpret_cast<const uint32_t*>(smf + VS_OFF);
    const uint32_t sbase = smem_u32(smf);

    const int m_tile = (int)gridDim.x - 1 - (int)blockIdx.x;  // longest first
    const int h  = blockIdx.y;
    const int b  = blockIdx.z;
    const int hk = h >> 2;
    const int m0 = m_tile * BM;
    const int NT = 4 * (m_tile + 1);

    const int tid  = threadIdx.x;
    const int wid  = tid >> 5;           // 0..3
    const int lane = tid & 31;
    const int lr   = lane >> 2;          // 0..7
    const int lc   = lane & 3;           // 0..3
    const int warp_m = wid * 32;         // warp owns rows warp_m..warp_m+31

    // ---- prefetch K(0), V(0) (V rows permuted: logical l -> slot (l>>1)+4*(l&1)) ----
    {
        #pragma unroll
        for (int j = 0; j < 8; ++j) {
            const int i = tid + j * NTHREADS;
            const int row = i >> 5, d4 = i & 31;
            const size_t gb = ((size_t)(b * PS + row) * PHKV + hk) * PD + (d4 << 2);
            cp16(sbase + (uint32_t)(KS_OFF + row * KS_STRIDE + (d4 << 2)) * 4u, k + gb);
        }
        #pragma unroll
        for (int j = 0; j < 8; ++j) {
            const int i = tid + j * NTHREADS;
            const int row = i >> 5, d4 = i & 31;
            const int vrow = (row & ~7) | ((row & 7) >> 1) | ((row & 1) << 2);
            const size_t gb = ((size_t)(b * PS + row) * PHKV + hk) * PD + (d4 << 2);
            cp16(sbase + (uint32_t)(VS_OFF + vrow * VS_STRIDE + (d4 << 2)) * 4u, v + gb);
        }
        cp_commit();
    }

    // ---- stage Q (tf32 rna, pre-scaled by (1/sqrt(D))*log2(e)) ----
    const float qscale = 0.08838834764831845f * 1.4426950408889634f;
    for (int i = tid; i < BM * (PD / 4); i += NTHREADS) {
        const int row = i >> 5, d4 = i & 31;
        const float4 val = *reinterpret_cast<const float4*>(
            q + ((size_t)(b * PS + m0 + row) * PHQ + h) * PD + (d4 << 2));
        uint4 t;
        t.x = tf32r(val.x * qscale); t.y = tf32r(val.y * qscale);
        t.z = tf32r(val.z * qscale); t.w = tf32r(val.w * qscale);
        *reinterpret_cast<uint4*>(QsU + row * QS_STRIDE + (d4 << 2)) = t;
    }

    float oc[2][16][4];                  // O accum: 32 rows x 128 cols per warp
    #pragma unroll
    for (int mi = 0; mi < 2; ++mi)
        #pragma unroll
        for (int ni = 0; ni < 16; ++ni)
            #pragma unroll
            for (int j = 0; j < 4; ++j) oc[mi][ni][j] = 0.0f;
    float ls[4] = {0.f, 0.f, 0.f, 0.f};  // [mi*2+half] row sums

    const int nt_last = 4 * m_tile + wid;  // last tile this warp computes

    for (int nt = 0; nt < NT; ++nt) {
        const int n0 = nt * BN;

        cp_wait<0>();      // K(nt) + V(nt) landed (own groups)
        __syncthreads();   // S2: K and V visible block-wide

        if (nt <= nt_last) {   // causal: skip tiles fully in this warp's future
            // ---- S = Q K^T : warp tile 32x32 (full BN), 2mi x 4ni x 16ks ----
            float sc[2][4][4];
            #pragma unroll
            for (int mi = 0; mi < 2; ++mi)
                #pragma unroll
                for (int ni = 0; ni < 4; ++ni)
                    #pragma unroll
                    for (int j = 0; j < 4; ++j) sc[mi][ni][j] = 0.0f;

            #pragma unroll
            for (int ks = 0; ks < 16; ++ks) {
                const int k0 = ks * 8;
                uint32_t a[2][4];
                #pragma unroll
                for (int mi = 0; mi < 2; ++mi) {
                    const uint32_t* q0 = QsU + (warp_m + mi * 16 + lr) * QS_STRIDE + k0 + lc;
                    a[mi][0] = q0[0];
                    a[mi][1] = q0[8 * QS_STRIDE];
                    a[mi][2] = q0[4];
                    a[mi][3] = q0[8 * QS_STRIDE + 4];
                }
                #pragma unroll
                for (int ni = 0; ni < 4; ++ni) {
                    const uint32_t* kp = KsU + (ni * 8 + lr) * KS_STRIDE + k0 + lc;
                    const uint32_t b0 = kp[0];
                    const uint32_t b1 = kp[4];
                    mma_tf32(sc[0][ni], a[0], b0, b1);
                    mma_tf32(sc[1][ni], a[1], b0, b1);
                }
            }

            // ---- softmax: p = exp2(s) unnormalized; mask only on this warp's diag ----
            const bool diag = (nt == nt_last);
            uint32_t pu[2][4][4];   // tf32 P fragments, order {p0,p2,p1,p3}
            #pragma unroll
            for (int mi = 0; mi < 2; ++mi) {
                const int r0g = m0 + warp_m + mi * 16 + lr;
                #pragma unroll
                for (int ni = 0; ni < 4; ++ni) {
                    const float* c = sc[mi][ni];
                    const int cb = n0 + ni * 8 + 2 * lc;
                    float p0, p1, p2, p3;
                    if (diag) {
                        p0 = (cb     <= r0g    ) ? ex2f(c[0]) : 0.0f;
                        p1 = (cb + 1 <= r0g    ) ? ex2f(c[1]) : 0.0f;
                        p2 = (cb     <= r0g + 8) ? ex2f(c[2]) : 0.0f;
                        p3 = (cb + 1 <= r0g + 8) ? ex2f(c[3]) : 0.0f;
                    } else {
                        p0 = ex2f(c[0]); p1 = ex2f(c[1]);
                        p2 = ex2f(c[2]); p3 = ex2f(c[3]);
                    }
                    ls[mi * 2 + 0] += p0 + p1;
                    ls[mi * 2 + 1] += p2 + p3;
                    pu[mi][ni][0] = tf32r(p0);
                    pu[mi][ni][1] = tf32r(p2);   // a1 = row+8, slot lc
                    pu[mi][ni][2] = tf32r(p1);   // a2 = row,   slot lc+4
                    pu[mi][ni][3] = tf32r(p3);
                }
            }

            // ---- O += P V : A = P from registers (V rows pre-permuted in smem) ----
            #pragma unroll
            for (int kp4 = 0; kp4 < 4; ++kp4) {      // k-chunk = S's ni group
                #pragma unroll
                for (int ni = 0; ni < 16; ++ni) {
                    const uint32_t* vp = VsU + (kp4 * 8 + lc) * VS_STRIDE + ni * 8 + lr;
                    const uint32_t b0 = vp[0];
                    const uint32_t b1 = vp[4 * VS_STRIDE];
                    mma_tf32(oc[0][ni], pu[0][kp4], b0, b1);
                    mma_tf32(oc[1][ni], pu[1][kp4], b0, b1);
                }
            }
        }

        __syncthreads();   // S1: all K/V reads done; buffers reusable

        if (nt + 1 < NT) {
            const int n1 = n0 + BN;
            #pragma unroll
            for (int j = 0; j < 8; ++j) {
                const int i = tid + j * NTHREADS;
                const int row = i >> 5, d4 = i & 31;
                const size_t gb = ((size_t)(b * PS + n1 + row) * PHKV + hk) * PD + (d4 << 2);
                cp16(sbase + (uint32_t)(KS_OFF + row * KS_STRIDE + (d4 << 2)) * 4u, k + gb);
            }
            #pragma unroll
            for (int j = 0; j < 8; ++j) {
                const int i = tid + j * NTHREADS;
                const int row = i >> 5, d4 = i & 31;
                const int vrow = (row & ~7) | ((row & 7) >> 1) | ((row & 1) << 2);
                const size_t gb = ((size_t)(b * PS + n1 + row) * PHKV + hk) * PD + (d4 << 2);
                cp16(sbase + (uint32_t)(VS_OFF + vrow * VS_STRIDE + (d4 << 2)) * 4u, v + gb);
            }
            cp_commit();
        }
    }

    // ---- epilogue: warp-private rowsums (quad reduce), normalize, store ----
    #pragma unroll
    for (int i = 0; i < 4; ++i) {
        ls[i] += __shfl_xor_sync(0xffffffffu, ls[i], 1);
        ls[i] += __shfl_xor_sync(0xffffffffu, ls[i], 2);
    }

    #pragma unroll
    for (int mi = 0; mi < 2; ++mi) {
        const float inv0 = 1.0f / ls[mi * 2 + 0];
        const float inv1 = 1.0f / ls[mi * 2 + 1];
        const int row0 = m0 + warp_m + mi * 16 + lr;
        float* op0 = out + ((size_t)(b * PS + row0) * PHQ + h) * PD + 2 * lc;
        float* op1 = out + ((size_t)(b * PS + row0 + 8) * PHQ + h) * PD + 2 * lc;
        #pragma unroll
        for (int ni = 0; ni < 16; ++ni) {
            float2 o0, o1;
            o0.x = oc[mi][ni][0] * inv0; o0.y = oc[mi][ni][1] * inv0;
            o1.x = oc[mi][ni][2] * inv1; o1.y = oc[mi][ni][3] * inv1;
            *reinterpret_cast<float2*>(op0 + ni * 8) = o0;
            *reinterpret_cast<float2*>(op1 + ni * 8) = o1;
        }
    }
}

extern "C" void kernel_launch(void* const* d_in, const int* in_sizes, int n_in,
                              void* d_out, int out_size) {
    // The reference's paged-cache scatter/gather is an exact identity
    // (distinct slots written then immediately gathered), so only q,k,v matter.
    const float* q = (const float*)d_in[0];
    const float* k = (const float*)d_in[1];
    const float* v = (const float*)d_in[2];
    float* out = (float*)d_out;

    cudaFuncSetAttribute(fa_mma5_kernel,
                         cudaFuncAttributeMaxDynamicSharedMemorySize, SMEM_BYTES);

    dim3 grid(PS / BM, PHQ, PB);   // (8, 32, 8) = 2048 CTAs
    fa_mma5_kernel<<<grid, NTHREADS, SMEM_BYTES>>>(q, k, v, out);
}